// round 6
// baseline (speedup 1.0000x reference)
#include <cuda_runtime.h>
#include <cstdint>
#include <cstddef>

#define E_TOTAL 400000
#define DIM 128
#define G_TOTAL 512
#define BM 128
#define NTHREADS 256

#define SSTR_A 132                    // H / A-slot stride (132 mod 32 = 4 -> conflict-free)
#define SSTR_B 68                     // W chunk stride   (68 mod 32 = 4 -> conflict-free)
#define NCHUNK_TOT 8                  // 6 layer-1 chunks (K=64) + 2 layer-2 chunks
#define CHUNK_WORDS (DIM * SSTR_B)    // 8704 words = 34816 B per weight image
#define SMEM_BYTES ((BM * SSTR_A + DIM * SSTR_B) * 4)   // 67584 + 34816 = 102400

// Scratch (static device arrays allowed; allocation is not)
__device__ float g_UB[G_TOTAL * DIM];                       // u @ W1[384:512] + b1 (fp32 exact)
__device__ __align__(16) float g_W[NCHUNK_TOT * CHUNK_WORDS]; // tf32 weights, [chunk][n][k] padded
__device__ int   g_batch[E_TOTAL];

__device__ __forceinline__ float to_tf32(float x) {
    unsigned r;
    asm("cvt.rna.tf32.f32 %0, %1;" : "=r"(r) : "f"(x));
    return __uint_as_float(r);
}
__device__ __forceinline__ void cp_async16(uint32_t dst_smem, const void* src) {
    asm volatile("cp.async.cg.shared.global [%0], [%1], 16;\n" :: "r"(dst_smem), "l"(src));
}
__device__ __forceinline__ void cp_async_commit() {
    asm volatile("cp.async.commit_group;\n" ::: "memory");
}
__device__ __forceinline__ void cp_async_wait0() {
    asm volatile("cp.async.wait_group 0;\n" ::: "memory");
}
__device__ __forceinline__ void mma_tf32(float* c, const unsigned* a, unsigned b0, unsigned b1) {
    asm volatile(
        "mma.sync.aligned.m16n8k8.row.col.f32.tf32.tf32.f32 "
        "{%0,%1,%2,%3},{%4,%5,%6,%7},{%8,%9},{%0,%1,%2,%3};\n"
        : "+f"(c[0]), "+f"(c[1]), "+f"(c[2]), "+f"(c[3])
        : "r"(a[0]), "r"(a[1]), "r"(a[2]), "r"(a[3]), "r"(b0), "r"(b1));
}

// ---------------------------------------------------------------------------
// batch may arrive as int32 (JAX x64 disabled) or int64. batch is sorted over
// 400k draws from [0,512); if int64, the high word of the last element is 0;
// if int32, that word is the last (largest) element, nonzero w.h.p.
// ---------------------------------------------------------------------------
__global__ void batch_norm_kernel(const int* __restrict__ bp32) {
    bool is64 = (bp32[E_TOTAL - 1] == 0);
    int i = blockIdx.x * blockDim.x + threadIdx.x;
    if (i < E_TOTAL)
        g_batch[i] = is64 ? (int)(((const long long*)bp32)[i]) : bp32[i];
}

// UB[g][n] = b1[n] + sum_k u[g][k] * W1[384+k][n]   (exact fp32, tiny)
__global__ void ub_kernel(const float* __restrict__ u, const float* __restrict__ W1,
                          const float* __restrict__ b1) {
    __shared__ float us[DIM];
    int gi = blockIdx.x, n = threadIdx.x;
    us[n] = u[gi * DIM + n];
    __syncthreads();
    float acc = b1[n];
    const float* w = W1 + 3 * DIM * DIM + n;
#pragma unroll 8
    for (int k = 0; k < DIM; ++k) acc += us[k] * w[k * DIM];
    g_UB[gi * DIM + n] = acc;
}

// One-time weight transform. Chunk c (c<6): K rows [c*64, c*64+64) of W1;
// c in {6,7}: rows of W2. Image layout [n][kk] with stride 68 (pads stay 0).
__global__ void wconv_kernel(const float* __restrict__ W1, const float* __restrict__ W2) {
    int c = blockIdx.x, n = blockIdx.y, kk = threadIdx.x;
    float v = (c < 6) ? W1[(c * 64 + kk) * DIM + n]
                      : W2[((c - 6) * 64 + kk) * DIM + n];
    g_W[c * CHUNK_WORDS + n * SSTR_B + kk] = to_tf32(v);
}

// 8 k-steps of m16n8k8 over a K=64 chunk.
// A: base Ab, row stride SSTR_A. B: base Bb, row stride SSTR_B.
__device__ __forceinline__ void mma_block64(const float* __restrict__ Ab,
                                            const float* __restrict__ Bb,
                                            float acc[2][8][4],
                                            int wm, int wn, int g, int tg) {
#pragma unroll
    for (int ks = 0; ks < 8; ++ks) {
        const int k0 = ks * 8;
        unsigned a[2][4];
#pragma unroll
        for (int mi = 0; mi < 2; ++mi) {
            const int r = wm * 32 + mi * 16;
            a[mi][0] = __float_as_uint(Ab[(r + g) * SSTR_A + k0 + tg]);
            a[mi][1] = __float_as_uint(Ab[(r + g + 8) * SSTR_A + k0 + tg]);
            a[mi][2] = __float_as_uint(Ab[(r + g) * SSTR_A + k0 + tg + 4]);
            a[mi][3] = __float_as_uint(Ab[(r + g + 8) * SSTR_A + k0 + tg + 4]);
        }
#pragma unroll
        for (int ni = 0; ni < 8; ++ni) {
            const int n = wn * 64 + ni * 8;
            unsigned b0 = __float_as_uint(Bb[(n + g) * SSTR_B + k0 + tg]);
            unsigned b1 = __float_as_uint(Bb[(n + g) * SSTR_B + k0 + tg + 4]);
            mma_tf32(acc[0][ni], a[0], b0, b1);
            mma_tf32(acc[1][ni], a[1], b0, b1);
        }
    }
}

__global__ __launch_bounds__(NTHREADS, 2)
void edge_mlp_kernel(const float* __restrict__ src, const float* __restrict__ dst,
                     const float* __restrict__ edge,
                     const float* __restrict__ b2, float* __restrict__ out) {
    extern __shared__ float smem[];
    float* sA = smem;                        // [128][132]: 2 A-chunk slots / full H
    float* sB = smem + BM * SSTR_A;          // [128][68]:  one weight chunk
    const uint32_t sB_u32 = (uint32_t)__cvta_generic_to_shared(sB);

    const int tid = threadIdx.x;
    const int warp = tid >> 5, lane = tid & 31;
    const int wm = warp & 3, wn = warp >> 2;
    const int g = lane >> 2, tg = lane & 3;
    const int e0 = blockIdx.x * BM;

    float acc[2][8][4];
#pragma unroll
    for (int mi = 0; mi < 2; ++mi)
#pragma unroll
        for (int ni = 0; ni < 8; ++ni)
#pragma unroll
            for (int j = 0; j < 4; ++j) acc[mi][ni][j] = 0.f;

    const float* parts[3] = {src, dst, edge};

    // ---------------- layer 1: six K=64 chunks ----------------
#pragma unroll 1
    for (int j = 0; j < 6; ++j) {
        const int slot = (j & 1) * 64;       // A slot column offset (64 == 0 mod 32 banks)
        __syncthreads();                     // prior chunk's mma readers done with sA/sB
        // kick weight image copy first (async under the A staging)
        {
            const float* wsrc = g_W + (size_t)j * CHUNK_WORDS;
#pragma unroll
            for (int t = 0; t < 9; ++t) {
                int i = t * NTHREADS + tid;  // float4 index
                if (i < CHUNK_WORDS / 4)
                    cp_async16(sB_u32 + i * 16, wsrc + i * 4);
            }
            cp_async_commit();
        }
        // A chunk: LDG.128 -> cvt.rna.tf32 -> STS.128 into slot
        {
            const float* Ap = parts[j >> 1] + (j & 1) * 64;
#pragma unroll
            for (int t = 0; t < 8; ++t) {
                int i = t * NTHREADS + tid;  // float4 id within 128x64 chunk
                int row = i >> 4, c4 = (i & 15) << 2;
                float4 v = *reinterpret_cast<const float4*>(
                    Ap + (size_t)(e0 + row) * DIM + c4);
                float4 q = make_float4(to_tf32(v.x), to_tf32(v.y),
                                       to_tf32(v.z), to_tf32(v.w));
                *reinterpret_cast<float4*>(sA + row * SSTR_A + slot + c4) = q;
            }
        }
        cp_async_wait0();
        __syncthreads();
        mma_block64(sA + slot, sB, acc, wm, wn, g, tg);
    }

    __syncthreads();                         // all warps done reading sA slots

    // ------ epilogue 1: + UB[batch] gather, relu, H -> sA (full 128 cols) ------
#pragma unroll
    for (int mi = 0; mi < 2; ++mi) {
        const int rA = wm * 32 + mi * 16 + g;
        const int rB = rA + 8;
        const int ga = g_batch[e0 + rA];
        const int gb = g_batch[e0 + rB];
#pragma unroll
        for (int ni = 0; ni < 8; ++ni) {
            const int c = wn * 64 + ni * 8 + tg * 2;
            float2 ua = *reinterpret_cast<const float2*>(g_UB + (size_t)ga * DIM + c);
            float2 ub = *reinterpret_cast<const float2*>(g_UB + (size_t)gb * DIM + c);
            float h0 = fmaxf(acc[mi][ni][0] + ua.x, 0.f);
            float h1 = fmaxf(acc[mi][ni][1] + ua.y, 0.f);
            float h2 = fmaxf(acc[mi][ni][2] + ub.x, 0.f);
            float h3 = fmaxf(acc[mi][ni][3] + ub.y, 0.f);
            *reinterpret_cast<float2*>(sA + rA * SSTR_A + c) =
                make_float2(to_tf32(h0), to_tf32(h1));
            *reinterpret_cast<float2*>(sA + rB * SSTR_A + c) =
                make_float2(to_tf32(h2), to_tf32(h3));
        }
    }

    // reset accumulators for layer 2
#pragma unroll
    for (int mi = 0; mi < 2; ++mi)
#pragma unroll
        for (int ni = 0; ni < 8; ++ni)
#pragma unroll
            for (int j = 0; j < 4; ++j) acc[mi][ni][j] = 0.f;

    // ---------------- layer 2: out = H @ W2, two K=64 chunks ----------------
#pragma unroll 1
    for (int c = 0; c < 2; ++c) {
        __syncthreads();                     // H writes visible / sB readers done
        {
            const float* wsrc = g_W + (size_t)(6 + c) * CHUNK_WORDS;
#pragma unroll
            for (int t = 0; t < 9; ++t) {
                int i = t * NTHREADS + tid;
                if (i < CHUNK_WORDS / 4)
                    cp_async16(sB_u32 + i * 16, wsrc + i * 4);
            }
            cp_async_commit();
            cp_async_wait0();
        }
        __syncthreads();
        mma_block64(sA + c * 64, sB, acc, wm, wn, g, tg);
    }

    // ---------------- epilogue 2: + b2, fp32 store ----------------
#pragma unroll
    for (int mi = 0; mi < 2; ++mi) {
        const int rA = wm * 32 + mi * 16 + g;
        const int rB = rA + 8;
#pragma unroll
        for (int ni = 0; ni < 8; ++ni) {
            const int c = wn * 64 + ni * 8 + tg * 2;
            float2 bv = *reinterpret_cast<const float2*>(b2 + c);
            *reinterpret_cast<float2*>(out + (size_t)(e0 + rA) * DIM + c) =
                make_float2(acc[mi][ni][0] + bv.x, acc[mi][ni][1] + bv.y);
            *reinterpret_cast<float2*>(out + (size_t)(e0 + rB) * DIM + c) =
                make_float2(acc[mi][ni][2] + bv.x, acc[mi][ni][3] + bv.y);
        }
    }
}

extern "C" void kernel_launch(void* const* d_in, const int* in_sizes, int n_in,
                              void* d_out, int out_size) {
    const float* src  = (const float*)d_in[0];
    const float* dst  = (const float*)d_in[1];
    const float* edge = (const float*)d_in[2];
    const float* u    = (const float*)d_in[3];
    const int*   bat  = (const int*)d_in[4];
    const float* W1   = (const float*)d_in[5];
    const float* b1   = (const float*)d_in[6];
    const float* W2   = (const float*)d_in[7];
    const float* b2   = (const float*)d_in[8];
    float* out = (float*)d_out;
    (void)in_sizes; (void)n_in; (void)out_size;

    cudaFuncSetAttribute(edge_mlp_kernel,
                         cudaFuncAttributeMaxDynamicSharedMemorySize, SMEM_BYTES);

    batch_norm_kernel<<<(E_TOTAL + 255) / 256, 256>>>(bat);
    ub_kernel<<<G_TOTAL, DIM>>>(u, W1, b1);
    wconv_kernel<<<dim3(NCHUNK_TOT, DIM), 64>>>(W1, W2);
    edge_mlp_kernel<<<E_TOTAL / BM, NTHREADS, SMEM_BYTES>>>(src, dst, edge, b2, out);
}

// round 9
// speedup vs baseline: 2.0830x; 2.0830x over previous
#include <cuda_runtime.h>
#include <cuda_fp16.h>
#include <cstdint>
#include <cstddef>

#define E_TOTAL 400000
#define DIM 128
#define G_TOTAL 512
#define BM 128
#define NTHREADS 256
#define SSTR 136                         // halves; 272B rows -> conflict-free ldmatrix
#define CHUNK_HALVES (DIM * SSTR)        // 17408 halves = 34816 B per image
#define SMEM_BYTES (2 * CHUNK_HALVES * 2)   // sA + sB = 69632 B

// Scratch (static device arrays allowed; allocation is not)
__device__ float  g_UB[G_TOTAL * DIM];                    // u @ W1[384:512] + b1 (fp32 exact)
__device__ __align__(16) __half g_W[4 * CHUNK_HALVES];    // fp16 weights, [chunk][n][k] stride 136
__device__ int    g_batch[E_TOTAL];

__device__ __forceinline__ void cp_async16(uint32_t dst_smem, const void* src) {
    asm volatile("cp.async.cg.shared.global [%0], [%1], 16;\n" :: "r"(dst_smem), "l"(src));
}
__device__ __forceinline__ void cp_async_commit() {
    asm volatile("cp.async.commit_group;\n" ::: "memory");
}
__device__ __forceinline__ void cp_async_wait0() {
    asm volatile("cp.async.wait_group 0;\n" ::: "memory");
}
__device__ __forceinline__ void ldsm4(unsigned& r0, unsigned& r1, unsigned& r2, unsigned& r3,
                                      uint32_t addr) {
    asm volatile("ldmatrix.sync.aligned.m8n8.x4.shared.b16 {%0,%1,%2,%3}, [%4];"
                 : "=r"(r0), "=r"(r1), "=r"(r2), "=r"(r3) : "r"(addr));
}
__device__ __forceinline__ void mma16816(float* c, const unsigned* a, unsigned b0, unsigned b1) {
    asm volatile(
        "mma.sync.aligned.m16n8k16.row.col.f32.f16.f16.f32 "
        "{%0,%1,%2,%3},{%4,%5,%6,%7},{%8,%9},{%0,%1,%2,%3};\n"
        : "+f"(c[0]), "+f"(c[1]), "+f"(c[2]), "+f"(c[3])
        : "r"(a[0]), "r"(a[1]), "r"(a[2]), "r"(a[3]), "r"(b0), "r"(b1));
}

// ---------------------------------------------------------------------------
// batch may arrive as int32 (JAX x64 disabled) or int64 (see R1 notes).
// ---------------------------------------------------------------------------
__global__ void batch_norm_kernel(const int* __restrict__ bp32) {
    bool is64 = (bp32[E_TOTAL - 1] == 0);
    int i = blockIdx.x * blockDim.x + threadIdx.x;
    if (i < E_TOTAL)
        g_batch[i] = is64 ? (int)(((const long long*)bp32)[i]) : bp32[i];
}

// UB[g][n] = b1[n] + sum_k u[g][k] * W1[384+k][n]   (exact fp32, tiny)
__global__ void ub_kernel(const float* __restrict__ u, const float* __restrict__ W1,
                          const float* __restrict__ b1) {
    __shared__ float us[DIM];
    int gi = blockIdx.x, n = threadIdx.x;
    us[n] = u[gi * DIM + n];
    __syncthreads();
    float acc = b1[n];
    const float* w = W1 + 3 * DIM * DIM + n;
#pragma unroll 8
    for (int k = 0; k < DIM; ++k) acc += us[k] * w[k * DIM];
    g_UB[gi * DIM + n] = acc;
}

// One-time weight transform: chunk c<3 -> W1 K-rows [c*128,c*128+128); c=3 -> W2.
// Image [n][k] halves, stride 136 (pads stay 0 in bss).
__global__ void wconv_kernel(const float* __restrict__ W1, const float* __restrict__ W2) {
    int c = blockIdx.x, n = blockIdx.y, k = threadIdx.x;
    float v = (c < 3) ? W1[(c * DIM + k) * DIM + n] : W2[k * DIM + n];
    g_W[c * CHUNK_HALVES + n * SSTR + k] = __float2half_rn(v);
}

// 8 k16-steps over a K=128 chunk via ldmatrix + mma.m16n8k16.
__device__ __forceinline__ void mma_block(const uint32_t aB[2], const uint32_t bB[4],
                                          float acc[2][8][4]) {
#pragma unroll
    for (int ks = 0; ks < 8; ++ks) {
        const uint32_t ko = ks * 32;          // 16 halves = 32 bytes
        unsigned a[2][4];
        ldsm4(a[0][0], a[0][1], a[0][2], a[0][3], aB[0] + ko);
        ldsm4(a[1][0], a[1][1], a[1][2], a[1][3], aB[1] + ko);
#pragma unroll
        for (int p = 0; p < 4; ++p) {
            unsigned b0, b1, b2, b3;
            ldsm4(b0, b1, b2, b3, bB[p] + ko);
            mma16816(acc[0][2 * p + 0], a[0], b0, b1);
            mma16816(acc[0][2 * p + 1], a[0], b2, b3);
            mma16816(acc[1][2 * p + 0], a[1], b0, b1);
            mma16816(acc[1][2 * p + 1], a[1], b2, b3);
        }
    }
}

// Load one 128x128 fp32 chunk into registers (16 float4 / thread).
__device__ __forceinline__ void ldg_chunk(const float* __restrict__ Ap, int e0, int tid,
                                          float4 pf[16]) {
#pragma unroll
    for (int it = 0; it < 16; ++it) {
        int i = it * NTHREADS + tid;
        int row = i >> 5, c4 = (i & 31) << 2;
        pf[it] = *reinterpret_cast<const float4*>(Ap + (size_t)(e0 + row) * DIM + c4);
    }
}

// Convert to fp16 + store into sA. Warp writes one row -> conflict-free.
__device__ __forceinline__ void sts_chunk(__half* __restrict__ sA, int tid,
                                          const float4 pf[16]) {
#pragma unroll
    for (int it = 0; it < 16; ++it) {
        int i = it * NTHREADS + tid;
        int row = i >> 5, c4 = (i & 31) << 2;
        __half2 h0 = __floats2half2_rn(pf[it].x, pf[it].y);
        __half2 h1 = __floats2half2_rn(pf[it].z, pf[it].w);
        *reinterpret_cast<__half2*>(sA + row * SSTR + c4) = h0;
        *reinterpret_cast<__half2*>(sA + row * SSTR + c4 + 2) = h1;
    }
}

__global__ __launch_bounds__(NTHREADS, 1)
void edge_mlp_kernel(const float* __restrict__ src, const float* __restrict__ dst,
                     const float* __restrict__ edge,
                     const float* __restrict__ b2, float* __restrict__ out) {
    extern __shared__ __half smem_h[];
    __half* sA = smem_h;                  // [128][136] halves: A chunk / H
    __half* sB = smem_h + CHUNK_HALVES;   // [128][136] halves: weight chunk [n][k]
    const uint32_t sA_u32 = (uint32_t)__cvta_generic_to_shared(sA);
    const uint32_t sB_u32 = (uint32_t)__cvta_generic_to_shared(sB);

    const int tid = threadIdx.x;
    const int warp = tid >> 5, lane = tid & 31;
    const int wm = warp & 3, wn = warp >> 2;
    const int g = lane >> 2, tg = lane & 3;
    const int e0 = blockIdx.x * BM;

    // per-lane ldmatrix base addresses (bytes, shared space)
    const int q = lane >> 3, rr = lane & 7;
    uint32_t aB[2], bB[4];
#pragma unroll
    for (int mi = 0; mi < 2; ++mi) {
        int row = wm * 32 + mi * 16 + rr + (q & 1) * 8;
        int kof = (q >> 1) * 8;
        aB[mi] = sA_u32 + (row * SSTR + kof) * 2;
    }
#pragma unroll
    for (int p = 0; p < 4; ++p) {
        int n = wn * 64 + p * 16 + rr + (q >> 1) * 8;
        int kof = (q & 1) * 8;
        bB[p] = sB_u32 + (n * SSTR + kof) * 2;
    }

    float acc[2][8][4];
#pragma unroll
    for (int mi = 0; mi < 2; ++mi)
#pragma unroll
        for (int ni = 0; ni < 8; ++ni)
#pragma unroll
            for (int j = 0; j < 4; ++j) acc[mi][ni][j] = 0.f;

    const float* parts[3] = {src, dst, edge};
    float4 pf[16];
    ldg_chunk(parts[0], e0, tid, pf);          // prefetch chunk 0

    // ---------------- layer 1: three K=128 chunks ----------------
#pragma unroll 1
    for (int part = 0; part < 3; ++part) {
        __syncthreads();                       // prior sA/sB readers done
        // weight chunk -> sB via linear cp.async (pre-converted fp16, conflict-free)
        {
            const __half* wsrc = g_W + (size_t)part * CHUNK_HALVES;
#pragma unroll
            for (int it = 0; it < 9; ++it) {
                int i = it * NTHREADS + tid;   // 16B unit
                if (i < (CHUNK_HALVES * 2) / 16)
                    cp_async16(sB_u32 + i * 16, (const char*)wsrc + i * 16);
            }
            cp_async_commit();
        }
        sts_chunk(sA, tid, pf);                // convert + store current A chunk
        if (part < 2) ldg_chunk(parts[part + 1], e0, tid, pf);   // overlap next LDGs
        cp_async_wait0();
        __syncthreads();
        mma_block(aB, bB, acc);
    }

    __syncthreads();                           // all warps done reading sA/sB

    // kick W2 staging early; overlaps epilogue 1
    {
        const __half* wsrc = g_W + (size_t)3 * CHUNK_HALVES;
#pragma unroll
        for (int it = 0; it < 9; ++it) {
            int i = it * NTHREADS + tid;
            if (i < (CHUNK_HALVES * 2) / 16)
                cp_async16(sB_u32 + i * 16, (const char*)wsrc + i * 16);
        }
        cp_async_commit();
    }

    // ------ epilogue 1: + UB[batch] gather, relu, H -> sA (fp16) ------
    // bank = (4g + tg + const) mod 32 -> all 32 banks distinct: conflict-free
#pragma unroll
    for (int mi = 0; mi < 2; ++mi) {
        const int rA = wm * 32 + mi * 16 + g;
        const int rB = rA + 8;
        const int ga = g_batch[e0 + rA];
        const int gb = g_batch[e0 + rB];
#pragma unroll
        for (int ni = 0; ni < 8; ++ni) {
            const int c = wn * 64 + ni * 8 + tg * 2;
            float2 ua = *reinterpret_cast<const float2*>(g_UB + (size_t)ga * DIM + c);
            float2 ub = *reinterpret_cast<const float2*>(g_UB + (size_t)gb * DIM + c);
            float h0 = fmaxf(acc[mi][ni][0] + ua.x, 0.f);
            float h1 = fmaxf(acc[mi][ni][1] + ua.y, 0.f);
            float h2 = fmaxf(acc[mi][ni][2] + ub.x, 0.f);
            float h3 = fmaxf(acc[mi][ni][3] + ub.y, 0.f);
            *reinterpret_cast<__half2*>(sA + rA * SSTR + c) = __floats2half2_rn(h0, h1);
            *reinterpret_cast<__half2*>(sA + rB * SSTR + c) = __floats2half2_rn(h2, h3);
        }
    }

    // reset accumulators for layer 2
#pragma unroll
    for (int mi = 0; mi < 2; ++mi)
#pragma unroll
        for (int ni = 0; ni < 8; ++ni)
#pragma unroll
            for (int j = 0; j < 4; ++j) acc[mi][ni][j] = 0.f;

    cp_async_wait0();
    __syncthreads();

    // ---------------- layer 2: out = H @ W2 ----------------
    mma_block(aB, bB, acc);

    // ---------------- epilogue 2: + b2, fp32 store ----------------
#pragma unroll
    for (int mi = 0; mi < 2; ++mi) {
        const int rA = wm * 32 + mi * 16 + g;
        const int rB = rA + 8;
#pragma unroll
        for (int ni = 0; ni < 8; ++ni) {
            const int c = wn * 64 + ni * 8 + tg * 2;
            float2 bv = *reinterpret_cast<const float2*>(b2 + c);
            *reinterpret_cast<float2*>(out + (size_t)(e0 + rA) * DIM + c) =
                make_float2(acc[mi][ni][0] + bv.x, acc[mi][ni][1] + bv.y);
            *reinterpret_cast<float2*>(out + (size_t)(e0 + rB) * DIM + c) =
                make_float2(acc[mi][ni][2] + bv.x, acc[mi][ni][3] + bv.y);
        }
    }
}

extern "C" void kernel_launch(void* const* d_in, const int* in_sizes, int n_in,
                              void* d_out, int out_size) {
    const float* src  = (const float*)d_in[0];
    const float* dst  = (const float*)d_in[1];
    const float* edge = (const float*)d_in[2];
    const float* u    = (const float*)d_in[3];
    const int*   bat  = (const int*)d_in[4];
    const float* W1   = (const float*)d_in[5];
    const float* b1   = (const float*)d_in[6];
    const float* W2   = (const float*)d_in[7];
    const float* b2   = (const float*)d_in[8];
    float* out = (float*)d_out;
    (void)in_sizes; (void)n_in; (void)out_size;

    cudaFuncSetAttribute(edge_mlp_kernel,
                         cudaFuncAttributeMaxDynamicSharedMemorySize, SMEM_BYTES);

    batch_norm_kernel<<<(E_TOTAL + 255) / 256, 256>>>(bat);
    ub_kernel<<<G_TOTAL, DIM>>>(u, W1, b1);
    wconv_kernel<<<dim3(4, DIM), DIM>>>(W1, W2);
    edge_mlp_kernel<<<E_TOTAL / BM, NTHREADS, SMEM_BYTES>>>(src, dst, edge, b2, out);
}